// round 9
// baseline (speedup 1.0000x reference)
#include <cuda_runtime.h>
#include <cuda_fp16.h>
#include <cstdint>

// ---------------------------------------------------------------------------
// GraphSAGE: 3x SAGEConv(mean) + linear head.
// N=100000, E=3200000, dims 64 -> 64 -> 32 -> 16 -> 1
//
// v9 = v8 with the k5 aliasing bug fixed (dedicated t2/u2 buffers).
//   k0: gemm0 (persistent tiles) + edge histogram + lookback-state zeroing
//   k1: single-kernel decoupled-lookback scan (rs, cur, inv; resets cnt)
//   k2: CSR fill
//   k3: gather64
//   k4: gemm1
//   k5: gather32 + fused gemm2 -> t2/u2 (separate buffers!)
//   k6: gather16 (t2/u2) + fused head
// ---------------------------------------------------------------------------

#define N_NODES 100000
#define MAX_E   3200000

__device__ __half g_t[(size_t)N_NODES * 64];   // fp16 messages (layers 0,1)
__device__ float  g_u[(size_t)N_NODES * 64];
__device__ float  g_h[(size_t)N_NODES * 64];
__device__ __half g_t2[(size_t)N_NODES * 16];  // layer-2 messages
__device__ float  g_u2[(size_t)N_NODES * 16];  // layer-2 self term
__device__ float  g_inv[N_NODES];
__device__ int    g_cnt[N_NODES];              // stays 0 between calls
__device__ int    g_rs[N_NODES + 1];
__device__ int    g_cur[N_NODES];
__device__ int    g_csr[MAX_E];
__device__ unsigned long long g_look[512];     // lookback: state<<32 | value

static inline int cdiv(long long a, int b) { return (int)((a + b - 1) / b); }

// ---------------- f32x2 helpers ----------------
__device__ __forceinline__ unsigned long long dup2(float a) {
    unsigned long long r;
    asm("mov.b64 %0, {%1, %1};" : "=l"(r) : "f"(a));
    return r;
}
__device__ __forceinline__ unsigned long long pack2(float a, float b) {
    unsigned long long r;
    asm("mov.b64 %0, {%1, %2};" : "=l"(r) : "f"(a), "f"(b));
    return r;
}
__device__ __forceinline__ void unpack2(unsigned long long v, float& a, float& b) {
    asm("mov.b64 {%0, %1}, %2;" : "=f"(a), "=f"(b) : "l"(v));
}
__device__ __forceinline__ void fma2(unsigned long long& acc,
                                     unsigned long long x, unsigned long long w) {
    asm("fma.rn.f32x2 %0, %1, %2, %0;" : "+l"(acc) : "l"(x), "l"(w));
}

__device__ __forceinline__ void addh2(float2& a, unsigned int h) {
    __half2 hh = *reinterpret_cast<__half2*>(&h);
    float2 f = __half22float2(hh);
    a.x += f.x; a.y += f.y;
}
__device__ __forceinline__ void addu4(float2* acc, const uint4& v) {
    addh2(acc[0], v.x); addh2(acc[1], v.y);
    addh2(acc[2], v.z); addh2(acc[3], v.w);
}

// ---------------- k0: gemm0 (64->64) + hist + lookback zero ----------------
__global__ void __launch_bounds__(256)
gemm0_hist_kernel(const float* __restrict__ X,
                  const float* __restrict__ Wl, const float* __restrict__ Wr,
                  const float* __restrict__ B,
                  __half* __restrict__ T, float* __restrict__ U,
                  const int* __restrict__ dst, int* __restrict__ cnt,
                  unsigned long long* __restrict__ look,
                  int n, int ntiles, int e) {
    constexpr int DIN = 64, DOUT = 64;
    constexpr int WT = 8, BT = 64, XP = DIN + 4;

    extern __shared__ float sm[];
    float* sW = sm;                    // 64*128
    float* sX = sm + DIN * 2 * DOUT;   // 64*68

    if (blockIdx.x == 0) {
        for (int i = threadIdx.x; i < 512; i += 256) look[i] = 0ULL;
    }

    for (int i = threadIdx.x; i < DIN * DOUT; i += 256) {
        int k = i / DOUT, j = i % DOUT;
        sW[k * 2 * DOUT + 4 * (j >> 1) + (j & 1)]     = Wl[i];
        sW[k * 2 * DOUT + 4 * (j >> 1) + 2 + (j & 1)] = Wr[i];
    }

    int lane = threadIdx.x & 31;
    int warp = threadIdx.x >> 5;
    int p = lane;                      // single group per warp (P == 32)

    float2 bb = *reinterpret_cast<const float2*>(B + 2 * p);

    for (int tile = blockIdx.x; tile < ntiles; tile += gridDim.x) {
        int nbase = tile * BT;
        __syncthreads();
        for (int i = threadIdx.x; i < BT * (DIN / 4); i += 256) {
            int node = i / (DIN / 4), kq = i % (DIN / 4);
            int gn = nbase + node;
            float4 v = make_float4(0.f, 0.f, 0.f, 0.f);
            if (gn < n) v = *reinterpret_cast<const float4*>(X + (size_t)gn * DIN + 4 * kq);
            *reinterpret_cast<float4*>(&sX[node * XP + 4 * kq]) = v;
        }
        __syncthreads();

        int ln = warp * WT;

        unsigned long long aL0[4], aL1[4], aR0[4], aR1[4];
#pragma unroll
        for (int m = 0; m < 4; m++) {
            aL0[m] = 0ull; aL1[m] = 0ull;
            aR0[m] = dup2(bb.x); aR1[m] = dup2(bb.y);
        }

#pragma unroll 8
        for (int k = 0; k < DIN; k++) {
            float4 w = *reinterpret_cast<const float4*>(&sW[k * 2 * DOUT + 4 * p]);
            unsigned long long wl0 = dup2(w.x), wl1 = dup2(w.y);
            unsigned long long wr0 = dup2(w.z), wr1 = dup2(w.w);
            float xs[8];
#pragma unroll
            for (int m = 0; m < 8; m++) xs[m] = sX[(ln + m) * XP + k];
#pragma unroll
            for (int m = 0; m < 4; m++) {
                unsigned long long xp2 = pack2(xs[2 * m], xs[2 * m + 1]);
                fma2(aL0[m], xp2, wl0);
                fma2(aL1[m], xp2, wl1);
                fma2(aR0[m], xp2, wr0);
                fma2(aR1[m], xp2, wr1);
            }
        }

#pragma unroll
        for (int m = 0; m < 4; m++) {
            float l0a, l0b, l1a, l1b, r0a, r0b, r1a, r1b;
            unpack2(aL0[m], l0a, l0b);
            unpack2(aL1[m], l1a, l1b);
            unpack2(aR0[m], r0a, r0b);
            unpack2(aR1[m], r1a, r1b);
            int gn0 = nbase + ln + 2 * m;
            if (gn0 < n) {
                reinterpret_cast<__half2*>(T)[(size_t)gn0 * 32 + p] =
                    __floats2half2_rn(l0a, l1a);
                *reinterpret_cast<float2*>(&U[(size_t)gn0 * DOUT + 2 * p]) =
                    make_float2(r0a, r1a);
            }
            if (gn0 + 1 < n) {
                reinterpret_cast<__half2*>(T)[(size_t)(gn0 + 1) * 32 + p] =
                    __floats2half2_rn(l0b, l1b);
                *reinterpret_cast<float2*>(&U[(size_t)(gn0 + 1) * DOUT + 2 * p]) =
                    make_float2(r0b, r1b);
            }
        }
    }

    // edge histogram (cnt is 0 at call entry; scan resets it afterwards)
    for (int i = blockIdx.x * blockDim.x + threadIdx.x; i < e;
         i += gridDim.x * blockDim.x) {
        atomicAdd(&cnt[dst[i]], 1);
    }
}

// ---------------- k1: decoupled-lookback scan ----------------
__global__ void __launch_bounds__(256)
scan_kernel(int* __restrict__ cnt, int* __restrict__ rs, int* __restrict__ cur,
            float* __restrict__ inv, unsigned long long* __restrict__ look, int n) {
    __shared__ int sm[256];
    __shared__ int s_prefix;
    int tid = threadIdx.x;
    int b = blockIdx.x;
    int gi = b * 256 + tid;
    int v = (gi < n) ? cnt[gi] : 0;
    sm[tid] = v;
    __syncthreads();
#pragma unroll
    for (int off = 1; off < 256; off <<= 1) {
        int t = (tid >= off) ? sm[tid - off] : 0;
        __syncthreads();
        sm[tid] += t;
        __syncthreads();
    }
    int le = sm[tid] - v;
    int tot = sm[255];

    if (tid == 0) {
        unsigned long long pub = (b == 0)
            ? ((2ULL << 32) | (unsigned)tot)
            : ((1ULL << 32) | (unsigned)tot);
        atomicExch(&look[b], pub);
        int prefix = 0;
        if (b > 0) {
            int p = b - 1;
            while (true) {
                unsigned long long w;
                do { w = atomicAdd(&look[p], 0ULL); } while ((w >> 32) == 0ULL);
                prefix += (int)(w & 0xffffffffULL);
                if ((w >> 32) == 2ULL) break;
                --p;
            }
            atomicExch(&look[b], (2ULL << 32) | (unsigned)(prefix + tot));
        }
        s_prefix = prefix;
    }
    __syncthreads();

    if (gi < n) {
        int r = s_prefix + le;
        rs[gi] = r;
        cur[gi] = r;
        inv[gi] = 1.0f / fmaxf((float)v, 1.0f);
        cnt[gi] = 0;
        if (gi == n - 1) rs[n] = r + v;
    }
}

// ---------------- k2: CSR fill ----------------
__global__ void fill_kernel(const int* __restrict__ src, const int* __restrict__ dst,
                            int* __restrict__ cur, int* __restrict__ csr, int e) {
    int i = blockIdx.x * blockDim.x + threadIdx.x;
    if (i < e) {
        int p = atomicAdd(&cur[dst[i]], 1);
        csr[p] = src[i];
    }
}

// ---------------- k4: tiled dual GEMM (64 -> 32) ----------------
template <int DIN, int DOUT>
__global__ void __launch_bounds__(256)
gemm_kernel(const float* __restrict__ X,
            const float* __restrict__ Wl, const float* __restrict__ Wr,
            const float* __restrict__ B,
            __half* __restrict__ T, float* __restrict__ U,
            int n, int ntiles) {
    constexpr int P  = DOUT / 2;
    constexpr int G  = 32 / P;
    constexpr int WT = 8 * G;
    constexpr int BT = 8 * WT;
    constexpr int XP = DIN + 4;

    extern __shared__ float sm[];
    float* sW = sm;
    float* sX = sm + DIN * 2 * DOUT;

    for (int i = threadIdx.x; i < DIN * DOUT; i += 256) {
        int k = i / DOUT, j = i % DOUT;
        sW[k * 2 * DOUT + 4 * (j >> 1) + (j & 1)]     = Wl[i];
        sW[k * 2 * DOUT + 4 * (j >> 1) + 2 + (j & 1)] = Wr[i];
    }

    int lane = threadIdx.x & 31;
    int warp = threadIdx.x >> 5;
    int g = lane / P;
    int p = lane % P;

    float2 bb = *reinterpret_cast<const float2*>(B + 2 * p);

    for (int tile = blockIdx.x; tile < ntiles; tile += gridDim.x) {
        int nbase = tile * BT;
        __syncthreads();
        for (int i = threadIdx.x; i < BT * (DIN / 4); i += 256) {
            int node = i / (DIN / 4), kq = i % (DIN / 4);
            int gn = nbase + node;
            float4 v = make_float4(0.f, 0.f, 0.f, 0.f);
            if (gn < n) v = *reinterpret_cast<const float4*>(X + (size_t)gn * DIN + 4 * kq);
            *reinterpret_cast<float4*>(&sX[node * XP + 4 * kq]) = v;
        }
        __syncthreads();

        int ln = warp * WT + g * 8;

        unsigned long long aL0[4], aL1[4], aR0[4], aR1[4];
#pragma unroll
        for (int m = 0; m < 4; m++) {
            aL0[m] = 0ull; aL1[m] = 0ull;
            aR0[m] = dup2(bb.x); aR1[m] = dup2(bb.y);
        }

#pragma unroll 8
        for (int k = 0; k < DIN; k++) {
            float4 w = *reinterpret_cast<const float4*>(&sW[k * 2 * DOUT + 4 * p]);
            unsigned long long wl0 = dup2(w.x), wl1 = dup2(w.y);
            unsigned long long wr0 = dup2(w.z), wr1 = dup2(w.w);
            float xs[8];
#pragma unroll
            for (int m = 0; m < 8; m++) xs[m] = sX[(ln + m) * XP + k];
#pragma unroll
            for (int m = 0; m < 4; m++) {
                unsigned long long xp2 = pack2(xs[2 * m], xs[2 * m + 1]);
                fma2(aL0[m], xp2, wl0);
                fma2(aL1[m], xp2, wl1);
                fma2(aR0[m], xp2, wr0);
                fma2(aR1[m], xp2, wr1);
            }
        }

#pragma unroll
        for (int m = 0; m < 4; m++) {
            float l0a, l0b, l1a, l1b, r0a, r0b, r1a, r1b;
            unpack2(aL0[m], l0a, l0b);
            unpack2(aL1[m], l1a, l1b);
            unpack2(aR0[m], r0a, r0b);
            unpack2(aR1[m], r1a, r1b);
            int gn0 = nbase + ln + 2 * m;
            if (gn0 < n) {
                reinterpret_cast<__half2*>(T)[(size_t)gn0 * P + p] =
                    __floats2half2_rn(l0a, l1a);
                *reinterpret_cast<float2*>(&U[(size_t)gn0 * DOUT + 2 * p]) =
                    make_float2(r0a, r1a);
            }
            if (gn0 + 1 < n) {
                reinterpret_cast<__half2*>(T)[(size_t)(gn0 + 1) * P + p] =
                    __floats2half2_rn(l0b, l1b);
                *reinterpret_cast<float2*>(&U[(size_t)(gn0 + 1) * DOUT + 2 * p]) =
                    make_float2(r0b, r1b);
            }
        }
    }
}

// ---------------- k3: gather64 (pipelined, fp16 rows) ----------------
__global__ void __launch_bounds__(256)
gather64_kernel(const int* __restrict__ rs, const int* __restrict__ csr,
                const __half* __restrict__ T, const float* __restrict__ U,
                const float* __restrict__ inv, float* __restrict__ H, int n) {
    int node = (blockIdx.x * blockDim.x + threadIdx.x) >> 5;
    if (node >= n) return;
    int lane = threadIdx.x & 31;
    int q = lane >> 3, l8 = lane & 7;

    int beg = rs[node], end = rs[node + 1];
    float iv = inv[node];
    const uint4* T4 = reinterpret_cast<const uint4*>(T);   // 8 uint4 per row

    float2 aA[4] = {{0,0},{0,0},{0,0},{0,0}};
    float2 aB[4] = {{0,0},{0,0},{0,0},{0,0}};

    int i = beg;
    int s0, s1, s2, s3;
    bool have = (i + 16 <= end);
    if (have) {
        s0 = __ldg(csr + i + q);
        s1 = __ldg(csr + i + 4 + q);
        s2 = __ldg(csr + i + 8 + q);
        s3 = __ldg(csr + i + 12 + q);
    }
    while (have) {
        uint4 v0 = __ldg(T4 + (size_t)s0 * 8 + l8);
        uint4 v1 = __ldg(T4 + (size_t)s1 * 8 + l8);
        uint4 v2 = __ldg(T4 + (size_t)s2 * 8 + l8);
        uint4 v3 = __ldg(T4 + (size_t)s3 * 8 + l8);
        i += 16;
        have = (i + 16 <= end);
        if (have) {
            s0 = __ldg(csr + i + q);
            s1 = __ldg(csr + i + 4 + q);
            s2 = __ldg(csr + i + 8 + q);
            s3 = __ldg(csr + i + 12 + q);
        }
        addu4(aA, v0); addu4(aB, v1); addu4(aA, v2); addu4(aB, v3);
    }
    {
        int e0 = i + q, e1 = i + 4 + q, e2 = i + 8 + q, e3 = i + 12 + q;
        if (e0 < end) { int s = __ldg(csr + e0); addu4(aA, __ldg(T4 + (size_t)s * 8 + l8)); }
        if (e1 < end) { int s = __ldg(csr + e1); addu4(aB, __ldg(T4 + (size_t)s * 8 + l8)); }
        if (e2 < end) { int s = __ldg(csr + e2); addu4(aA, __ldg(T4 + (size_t)s * 8 + l8)); }
        if (e3 < end) { int s = __ldg(csr + e3); addu4(aB, __ldg(T4 + (size_t)s * 8 + l8)); }
    }
#pragma unroll
    for (int m = 0; m < 4; m++) { aA[m].x += aB[m].x; aA[m].y += aB[m].y; }
#pragma unroll
    for (int off = 8; off <= 16; off <<= 1) {
#pragma unroll
        for (int m = 0; m < 4; m++) {
            aA[m].x += __shfl_down_sync(0xffffffffu, aA[m].x, off);
            aA[m].y += __shfl_down_sync(0xffffffffu, aA[m].y, off);
        }
    }

    if (q == 0) {
        const float4* U4 = reinterpret_cast<const float4*>(U) + (size_t)node * 16 + l8 * 2;
        float4* H4 = reinterpret_cast<float4*>(H) + (size_t)node * 16 + l8 * 2;
        float4 u0 = __ldg(U4), u1 = __ldg(U4 + 1);
        float4 h0, h1;
        h0.x = fmaxf(fmaf(aA[0].x, iv, u0.x), 0.0f);
        h0.y = fmaxf(fmaf(aA[0].y, iv, u0.y), 0.0f);
        h0.z = fmaxf(fmaf(aA[1].x, iv, u0.z), 0.0f);
        h0.w = fmaxf(fmaf(aA[1].y, iv, u0.w), 0.0f);
        h1.x = fmaxf(fmaf(aA[2].x, iv, u1.x), 0.0f);
        h1.y = fmaxf(fmaf(aA[2].y, iv, u1.y), 0.0f);
        h1.z = fmaxf(fmaf(aA[3].x, iv, u1.z), 0.0f);
        h1.w = fmaxf(fmaf(aA[3].y, iv, u1.w), 0.0f);
        H4[0] = h0; H4[1] = h1;
    }
}

// ---------------- k5: gather32 + fused gemm2 (32 -> 16, dual) ----------------
__global__ void __launch_bounds__(256)
gather32_gemm2_kernel(const int* __restrict__ rs, const int* __restrict__ csr,
                      const __half* __restrict__ T, const float* __restrict__ U,
                      const float* __restrict__ inv,
                      const float* __restrict__ Wl2, const float* __restrict__ Wr2,
                      const float* __restrict__ B2,
                      __half* __restrict__ T2, float* __restrict__ U2, int n) {
    __shared__ float sW[32 * 32];     // [k][j]: j<16 -> Wl2, j>=16 -> Wr2
    __shared__ float sB[16];
    for (int i = threadIdx.x; i < 32 * 32; i += 256) {
        int k = i >> 5, j = i & 31;
        sW[i] = (j < 16) ? Wl2[k * 16 + j] : Wr2[k * 16 + (j - 16)];
    }
    if (threadIdx.x < 16) sB[threadIdx.x] = B2[threadIdx.x];
    __syncthreads();

    int node = (blockIdx.x * blockDim.x + threadIdx.x) >> 5;
    if (node >= n) return;
    int lane = threadIdx.x & 31;
    int g = lane >> 2, l4 = lane & 3;

    int beg = rs[node], end = rs[node + 1];
    float iv = inv[node];
    const uint4* T4 = reinterpret_cast<const uint4*>(T);   // 4 uint4 per row

    float2 aA[4] = {{0,0},{0,0},{0,0},{0,0}};
    float2 aB[4] = {{0,0},{0,0},{0,0},{0,0}};

    int i = beg;
    int s0, s1;
    bool have = (i + 16 <= end);
    if (have) {
        s0 = __ldg(csr + i + g);
        s1 = __ldg(csr + i + 8 + g);
    }
    while (have) {
        uint4 v0 = __ldg(T4 + (size_t)s0 * 4 + l4);
        uint4 v1 = __ldg(T4 + (size_t)s1 * 4 + l4);
        i += 16;
        have = (i + 16 <= end);
        if (have) {
            s0 = __ldg(csr + i + g);
            s1 = __ldg(csr + i + 8 + g);
        }
        addu4(aA, v0); addu4(aB, v1);
    }
    {
        int e0 = i + g, e1 = i + 8 + g;
        if (e0 < end) { int s = __ldg(csr + e0); addu4(aA, __ldg(T4 + (size_t)s * 4 + l4)); }
        if (e1 < end) { int s = __ldg(csr + e1); addu4(aB, __ldg(T4 + (size_t)s * 4 + l4)); }
    }
#pragma unroll
    for (int m = 0; m < 4; m++) { aA[m].x += aB[m].x; aA[m].y += aB[m].y; }
#pragma unroll
    for (int off = 4; off <= 16; off <<= 1) {
#pragma unroll
        for (int m = 0; m < 4; m++) {
            aA[m].x += __shfl_down_sync(0xffffffffu, aA[m].x, off);
            aA[m].y += __shfl_down_sync(0xffffffffu, aA[m].y, off);
        }
    }

    float h[8] = {0, 0, 0, 0, 0, 0, 0, 0};
    if (g == 0) {
        const float4* U4 = reinterpret_cast<const float4*>(U) + (size_t)node * 8 + l4 * 2;
        float4 u0 = __ldg(U4), u1 = __ldg(U4 + 1);
        h[0] = fmaxf(fmaf(aA[0].x, iv, u0.x), 0.0f);
        h[1] = fmaxf(fmaf(aA[0].y, iv, u0.y), 0.0f);
        h[2] = fmaxf(fmaf(aA[1].x, iv, u0.z), 0.0f);
        h[3] = fmaxf(fmaf(aA[1].y, iv, u0.w), 0.0f);
        h[4] = fmaxf(fmaf(aA[2].x, iv, u1.x), 0.0f);
        h[5] = fmaxf(fmaf(aA[2].y, iv, u1.y), 0.0f);
        h[6] = fmaxf(fmaf(aA[3].x, iv, u1.z), 0.0f);
        h[7] = fmaxf(fmaf(aA[3].y, iv, u1.w), 0.0f);
    }

    // fused gemm2: lane j<16 -> t2[j], lane j>=16 -> u2[j-16]
    float acc = (lane < 16) ? 0.0f : sB[lane - 16];
#pragma unroll
    for (int k = 0; k < 32; k++) {
        float hk = __shfl_sync(0xffffffffu, h[k & 7], k >> 3);
        acc = fmaf(hk, sW[k * 32 + lane], acc);
    }

    if (lane < 16) T2[(size_t)node * 16 + lane] = __float2half(acc);
    else           U2[(size_t)node * 16 + (lane - 16)] = acc;
}

// ---------------- k6: gather16 + fused 16->1 head ----------------
__global__ void __launch_bounds__(256)
gather16_head_kernel(const int* __restrict__ rs, const int* __restrict__ csr,
                     const __half* __restrict__ T, const float* __restrict__ U,
                     const float* __restrict__ inv,
                     const float* __restrict__ Wc, const float* __restrict__ bc,
                     float* __restrict__ out, int n) {
    int node = (blockIdx.x * blockDim.x + threadIdx.x) >> 5;
    if (node >= n) return;
    int lane = threadIdx.x & 31;
    int g = lane >> 1, l2 = lane & 1;

    int beg = rs[node], end = rs[node + 1];
    float iv = inv[node];
    const uint4* T4 = reinterpret_cast<const uint4*>(T);   // 2 uint4 per row

    float2 aA[4] = {{0,0},{0,0},{0,0},{0,0}};
    float2 aB[4] = {{0,0},{0,0},{0,0},{0,0}};

    int i = beg;
    int s0, s1;
    bool have = (i + 32 <= end);
    if (have) {
        s0 = __ldg(csr + i + g);
        s1 = __ldg(csr + i + 16 + g);
    }
    while (have) {
        uint4 v0 = __ldg(T4 + (size_t)s0 * 2 + l2);
        uint4 v1 = __ldg(T4 + (size_t)s1 * 2 + l2);
        i += 32;
        have = (i + 32 <= end);
        if (have) {
            s0 = __ldg(csr + i + g);
            s1 = __ldg(csr + i + 16 + g);
        }
        addu4(aA, v0); addu4(aB, v1);
    }
    {
        int e0 = i + g, e1 = i + 16 + g;
        if (e0 < end) { int s = __ldg(csr + e0); addu4(aA, __ldg(T4 + (size_t)s * 2 + l2)); }
        if (e1 < end) { int s = __ldg(csr + e1); addu4(aB, __ldg(T4 + (size_t)s * 2 + l2)); }
    }
#pragma unroll
    for (int m = 0; m < 4; m++) { aA[m].x += aB[m].x; aA[m].y += aB[m].y; }
#pragma unroll
    for (int off = 2; off <= 16; off <<= 1) {
#pragma unroll
        for (int m = 0; m < 4; m++) {
            aA[m].x += __shfl_down_sync(0xffffffffu, aA[m].x, off);
            aA[m].y += __shfl_down_sync(0xffffffffu, aA[m].y, off);
        }
    }

    float partial = 0.0f;
    if (lane < 2) {
        const float4* U4 = reinterpret_cast<const float4*>(U) + (size_t)node * 4 + l2 * 2;
        float4 u0 = __ldg(U4), u1 = __ldg(U4 + 1);
        const float4* W4 = reinterpret_cast<const float4*>(Wc) + l2 * 2;
        float4 w0 = __ldg(W4), w1 = __ldg(W4 + 1);
        float h0 = fmaxf(fmaf(aA[0].x, iv, u0.x), 0.0f);
        float h1 = fmaxf(fmaf(aA[0].y, iv, u0.y), 0.0f);
        float h2 = fmaxf(fmaf(aA[1].x, iv, u0.z), 0.0f);
        float h3 = fmaxf(fmaf(aA[1].y, iv, u0.w), 0.0f);
        float h4 = fmaxf(fmaf(aA[2].x, iv, u1.x), 0.0f);
        float h5 = fmaxf(fmaf(aA[2].y, iv, u1.y), 0.0f);
        float h6 = fmaxf(fmaf(aA[3].x, iv, u1.z), 0.0f);
        float h7 = fmaxf(fmaf(aA[3].y, iv, u1.w), 0.0f);
        partial = h0 * w0.x + h1 * w0.y + h2 * w0.z + h3 * w0.w
                + h4 * w1.x + h5 * w1.y + h6 * w1.z + h7 * w1.w;
    }
    partial += __shfl_down_sync(0xffffffffu, partial, 1);
    if (lane == 0) out[node] = partial + __ldg(bc);
}

// ---------------------------------------------------------------------------

extern "C" void kernel_launch(void* const* d_in, const int* in_sizes, int n_in,
                              void* d_out, int out_size) {
    const float* x   = (const float*)d_in[0];
    const int* eidx  = (const int*)d_in[1];
    const float* Wl0 = (const float*)d_in[2];
    const float* Wr0 = (const float*)d_in[3];
    const float* b0  = (const float*)d_in[4];
    const float* Wl1 = (const float*)d_in[5];
    const float* Wr1 = (const float*)d_in[6];
    const float* b1  = (const float*)d_in[7];
    const float* Wl2 = (const float*)d_in[8];
    const float* Wr2 = (const float*)d_in[9];
    const float* b2  = (const float*)d_in[10];
    const float* Wc  = (const float*)d_in[11];
    const float* bc  = (const float*)d_in[12];
    float* out = (float*)d_out;

    const int n = in_sizes[0] / 64;        // 100000
    const int e = in_sizes[1] / 2;         // 3200000
    const int* src = eidx;
    const int* dst = eidx + e;

    __half *t, *t2;
    float *u, *h, *u2, *inv;
    int *cnt, *rs, *cur, *csr;
    unsigned long long* look;
    cudaGetSymbolAddress((void**)&t, g_t);
    cudaGetSymbolAddress((void**)&u, g_u);
    cudaGetSymbolAddress((void**)&h, g_h);
    cudaGetSymbolAddress((void**)&t2, g_t2);
    cudaGetSymbolAddress((void**)&u2, g_u2);
    cudaGetSymbolAddress((void**)&inv, g_inv);
    cudaGetSymbolAddress((void**)&cnt, g_cnt);
    cudaGetSymbolAddress((void**)&rs, g_rs);
    cudaGetSymbolAddress((void**)&cur, g_cur);
    cudaGetSymbolAddress((void**)&csr, g_csr);
    cudaGetSymbolAddress((void**)&look, g_look);

    // k0: gemm0 + hist + lookback zero
    {
        constexpr int SMEM = (64 * 128 + 64 * 68) * (int)sizeof(float);
        cudaFuncSetAttribute(gemm0_hist_kernel,
                             cudaFuncAttributeMaxDynamicSharedMemorySize, SMEM);
        int ntiles = cdiv(n, 64);
        gemm0_hist_kernel<<<592, 256, SMEM>>>(x, Wl0, Wr0, b0, t, u,
                                              dst, cnt, look, n, ntiles, e);
    }

    // k1: scan (rs, cur, inv; resets cnt)
    scan_kernel<<<cdiv(n, 256), 256>>>(cnt, rs, cur, inv, look, n);

    // k2: CSR fill
    fill_kernel<<<cdiv(e, 256), 256>>>(src, dst, cur, csr, e);

    // k3: gather64 -> h
    gather64_kernel<<<cdiv((long long)n * 32, 256), 256>>>(rs, csr, t, u, inv, h, n);

    // k4: gemm1 (64 -> 32)
    {
        constexpr int SMEM = (64 * 64 + 128 * 68) * (int)sizeof(float);
        cudaFuncSetAttribute(gemm_kernel<64, 32>,
                             cudaFuncAttributeMaxDynamicSharedMemorySize, SMEM);
        int ntiles = cdiv(n, 128);
        int grid = ntiles < 592 ? ntiles : 592;
        gemm_kernel<64, 32><<<grid, 256, SMEM>>>(h, Wl1, Wr1, b1, t, u, n, ntiles);
    }

    // k5: gather32 + fused gemm2 -> t2/u2 (separate buffers — no aliasing)
    gather32_gemm2_kernel<<<cdiv((long long)n * 32, 256), 256>>>(
        rs, csr, t, u, inv, Wl2, Wr2, b2, t2, u2, n);

    // k6: gather16 (t2/u2) + fused head -> out
    gather16_head_kernel<<<cdiv((long long)n * 32, 256), 256>>>(rs, csr, t2, u2, inv,
                                                                Wc, bc, out, n);
}

// round 10
// speedup vs baseline: 1.0887x; 1.0887x over previous
#include <cuda_runtime.h>
#include <cstdint>

// ---------------------------------------------------------------------------
// GraphSAGE: 3x SAGEConv(mean) + linear head.
// N=100000, E=3200000, dims 64 -> 64 -> 32 -> 16 -> 1
//
// v10: v7 launch structure (measured best) + instruction-minimal gathers:
//      fp32 T (no convert stream), add.rn.f32x2 packed accumulation,
//      pipelined multi-chain index prefetch, 32-bit address math.
//      ncu R9: gather was ISSUE-bound (fma 29% + alu 18%), not memory-bound.
// ---------------------------------------------------------------------------

#define N_NODES 100000
#define MAX_E   3200000

__device__ float g_t[(size_t)N_NODES * 64];
__device__ float g_u[(size_t)N_NODES * 64];
__device__ float g_h[(size_t)N_NODES * 64];
__device__ float g_inv[N_NODES];
__device__ int   g_cnt[N_NODES];
__device__ int   g_rs[N_NODES + 1];
__device__ int   g_cur[N_NODES];
__device__ int   g_csr[MAX_E];
__device__ int   g_bsum[512];

static inline int cdiv(long long a, int b) { return (int)((a + b - 1) / b); }

// ---------------- f32x2 helpers ----------------
__device__ __forceinline__ unsigned long long dup2(float a) {
    unsigned long long r;
    asm("mov.b64 %0, {%1, %1};" : "=l"(r) : "f"(a));
    return r;
}
__device__ __forceinline__ unsigned long long pack2(float a, float b) {
    unsigned long long r;
    asm("mov.b64 %0, {%1, %2};" : "=l"(r) : "f"(a), "f"(b));
    return r;
}
__device__ __forceinline__ void unpack2(unsigned long long v, float& a, float& b) {
    asm("mov.b64 {%0, %1}, %2;" : "=f"(a), "=f"(b) : "l"(v));
}
__device__ __forceinline__ void fma2(unsigned long long& acc,
                                     unsigned long long x, unsigned long long w) {
    asm("fma.rn.f32x2 %0, %1, %2, %0;" : "+l"(acc) : "l"(x), "l"(w));
}
__device__ __forceinline__ void add2(unsigned long long& acc, unsigned long long v) {
    asm("add.rn.f32x2 %0, %1, %2;" : "=l"(acc) : "l"(acc), "l"(v));
}

// ---------------- CSR build (v7 structure — measured good) ----------------
__global__ void zero_cnt_kernel(int* __restrict__ cnt, int n) {
    int i = blockIdx.x * blockDim.x + threadIdx.x;
    if (i < n) cnt[i] = 0;
}

__global__ void hist_kernel(const int* __restrict__ dst, int* __restrict__ cnt, int e) {
    int i = blockIdx.x * blockDim.x + threadIdx.x;
    if (i < e) atomicAdd(&cnt[dst[i]], 1);
}

__global__ void __launch_bounds__(256)
scan1_kernel(const int* __restrict__ cnt, int* __restrict__ rs,
             int* __restrict__ bsum, int n) {
    __shared__ int sm[256];
    int tid = threadIdx.x;
    int gi = blockIdx.x * 256 + tid;
    int v = (gi < n) ? cnt[gi] : 0;
    sm[tid] = v;
    __syncthreads();
#pragma unroll
    for (int off = 1; off < 256; off <<= 1) {
        int t = (tid >= off) ? sm[tid - off] : 0;
        __syncthreads();
        sm[tid] += t;
        __syncthreads();
    }
    if (gi < n) rs[gi] = sm[tid] - v;
    if (tid == 255) bsum[blockIdx.x] = sm[255];
}

__global__ void __launch_bounds__(512)
scan2_kernel(int* __restrict__ bsum, int nb) {
    __shared__ int sm[512];
    int tid = threadIdx.x;
    int v = (tid < nb) ? bsum[tid] : 0;
    sm[tid] = v;
    __syncthreads();
#pragma unroll
    for (int off = 1; off < 512; off <<= 1) {
        int t = (tid >= off) ? sm[tid - off] : 0;
        __syncthreads();
        sm[tid] += t;
        __syncthreads();
    }
    if (tid < nb) bsum[tid] = sm[tid] - v;
}

__global__ void scan3_kernel(const int* __restrict__ cnt, int* __restrict__ rs,
                             int* __restrict__ cur, float* __restrict__ inv,
                             const int* __restrict__ bsum, int n) {
    int gi = blockIdx.x * blockDim.x + threadIdx.x;
    if (gi >= n) return;
    int rsv = rs[gi] + bsum[blockIdx.x];
    rs[gi] = rsv;
    cur[gi] = rsv;
    int c = cnt[gi];
    inv[gi] = 1.0f / fmaxf((float)c, 1.0f);
    if (gi == n - 1) rs[n] = rsv + c;
}

__global__ void fill_kernel(const int* __restrict__ src, const int* __restrict__ dst,
                            int* __restrict__ cur, int* __restrict__ csr, int e) {
    int i = blockIdx.x * blockDim.x + threadIdx.x;
    if (i < e) {
        int p = atomicAdd(&cur[dst[i]], 1);
        csr[p] = src[i];
    }
}

// ---------------- tiled dual GEMM: t = X@Wl, u = X@Wr + b (fp32 out) --------
template <int DIN, int DOUT>
__global__ void __launch_bounds__(256)
gemm_kernel(const float* __restrict__ X,
            const float* __restrict__ Wl, const float* __restrict__ Wr,
            const float* __restrict__ B,
            float* __restrict__ T, float* __restrict__ U,
            int n, int ntiles) {
    constexpr int P  = DOUT / 2;
    constexpr int G  = 32 / P;
    constexpr int WT = 8 * G;
    constexpr int BT = 8 * WT;
    constexpr int XP = DIN + 4;

    extern __shared__ float sm[];
    float* sW = sm;
    float* sX = sm + DIN * 2 * DOUT;

    for (int i = threadIdx.x; i < DIN * DOUT; i += 256) {
        int k = i / DOUT, j = i % DOUT;
        sW[k * 2 * DOUT + 4 * (j >> 1) + (j & 1)]     = Wl[i];
        sW[k * 2 * DOUT + 4 * (j >> 1) + 2 + (j & 1)] = Wr[i];
    }

    int lane = threadIdx.x & 31;
    int warp = threadIdx.x >> 5;
    int g = lane / P;
    int p = lane % P;

    float2 bb = *reinterpret_cast<const float2*>(B + 2 * p);

    for (int tile = blockIdx.x; tile < ntiles; tile += gridDim.x) {
        int nbase = tile * BT;
        __syncthreads();
        for (int i = threadIdx.x; i < BT * (DIN / 4); i += 256) {
            int node = i / (DIN / 4), kq = i % (DIN / 4);
            int gn = nbase + node;
            float4 v = make_float4(0.f, 0.f, 0.f, 0.f);
            if (gn < n) v = *reinterpret_cast<const float4*>(X + (size_t)gn * DIN + 4 * kq);
            *reinterpret_cast<float4*>(&sX[node * XP + 4 * kq]) = v;
        }
        __syncthreads();

        int ln = warp * WT + g * 8;

        unsigned long long aL0[4], aL1[4], aR0[4], aR1[4];
#pragma unroll
        for (int m = 0; m < 4; m++) {
            aL0[m] = 0ull; aL1[m] = 0ull;
            aR0[m] = dup2(bb.x); aR1[m] = dup2(bb.y);
        }

#pragma unroll 8
        for (int k = 0; k < DIN; k++) {
            float4 w = *reinterpret_cast<const float4*>(&sW[k * 2 * DOUT + 4 * p]);
            unsigned long long wl0 = dup2(w.x), wl1 = dup2(w.y);
            unsigned long long wr0 = dup2(w.z), wr1 = dup2(w.w);
            float xs[8];
#pragma unroll
            for (int m = 0; m < 8; m++) xs[m] = sX[(ln + m) * XP + k];
#pragma unroll
            for (int m = 0; m < 4; m++) {
                unsigned long long xp2 = pack2(xs[2 * m], xs[2 * m + 1]);
                fma2(aL0[m], xp2, wl0);
                fma2(aL1[m], xp2, wl1);
                fma2(aR0[m], xp2, wr0);
                fma2(aR1[m], xp2, wr1);
            }
        }

#pragma unroll
        for (int m = 0; m < 4; m++) {
            float l0a, l0b, l1a, l1b, r0a, r0b, r1a, r1b;
            unpack2(aL0[m], l0a, l0b);
            unpack2(aL1[m], l1a, l1b);
            unpack2(aR0[m], r0a, r0b);
            unpack2(aR1[m], r1a, r1b);
            int gn0 = nbase + ln + 2 * m;
            if (gn0 < n) {
                *reinterpret_cast<float2*>(&T[(size_t)gn0 * DOUT + 2 * p]) = make_float2(l0a, l1a);
                *reinterpret_cast<float2*>(&U[(size_t)gn0 * DOUT + 2 * p]) = make_float2(r0a, r1a);
            }
            if (gn0 + 1 < n) {
                *reinterpret_cast<float2*>(&T[(size_t)(gn0 + 1) * DOUT + 2 * p]) = make_float2(l0b, l1b);
                *reinterpret_cast<float2*>(&U[(size_t)(gn0 + 1) * DOUT + 2 * p]) = make_float2(r0b, r1b);
            }
        }
    }
}

// ---------------- gathers: fp32 rows, f32x2 adds, pipelined chains ----------
// ulonglong2 == float4 == 16B. All row indices fit 32-bit.

// DOUT=64: row = 256B = 16 lanes x float4; 2 edges/LDG; 4 chains = 8 edges/iter.
__global__ void __launch_bounds__(256)
gather64_kernel(const int* __restrict__ rs, const int* __restrict__ csr,
                const float* __restrict__ T, const float* __restrict__ U,
                const float* __restrict__ inv, float* __restrict__ H, int n) {
    int node = (blockIdx.x * blockDim.x + threadIdx.x) >> 5;
    if (node >= n) return;
    int lane = threadIdx.x & 31;
    unsigned half = lane >> 4, l16 = lane & 15;

    int beg = rs[node], end = rs[node + 1];
    float iv = inv[node];
    const ulonglong2* Tp = reinterpret_cast<const ulonglong2*>(T);  // 16 per row

    unsigned long long a0 = 0, a1 = 0, b0 = 0, b1 = 0;

    int i = beg;
    int s0, s1, s2, s3;
    bool have = (i + 8 <= end);
    if (have) {
        s0 = __ldg(csr + i + half);
        s1 = __ldg(csr + i + 2 + half);
        s2 = __ldg(csr + i + 4 + half);
        s3 = __ldg(csr + i + 6 + half);
    }
    while (have) {
        ulonglong2 v0 = __ldg(Tp + (unsigned)s0 * 16u + l16);
        ulonglong2 v1 = __ldg(Tp + (unsigned)s1 * 16u + l16);
        ulonglong2 v2 = __ldg(Tp + (unsigned)s2 * 16u + l16);
        ulonglong2 v3 = __ldg(Tp + (unsigned)s3 * 16u + l16);
        i += 8;
        have = (i + 8 <= end);
        if (have) {
            s0 = __ldg(csr + i + half);
            s1 = __ldg(csr + i + 2 + half);
            s2 = __ldg(csr + i + 4 + half);
            s3 = __ldg(csr + i + 6 + half);
        }
        add2(a0, v0.x); add2(a1, v0.y);
        add2(b0, v1.x); add2(b1, v1.y);
        add2(a0, v2.x); add2(a1, v2.y);
        add2(b0, v3.x); add2(b1, v3.y);
    }
    {   // tail < 8 edges: predicated, all chains issue concurrently
        int e0 = i + half, e1 = i + 2 + half, e2 = i + 4 + half, e3 = i + 6 + half;
        if (e0 < end) { unsigned s = __ldg(csr + e0); ulonglong2 v = __ldg(Tp + s * 16u + l16); add2(a0, v.x); add2(a1, v.y); }
        if (e1 < end) { unsigned s = __ldg(csr + e1); ulonglong2 v = __ldg(Tp + s * 16u + l16); add2(b0, v.x); add2(b1, v.y); }
        if (e2 < end) { unsigned s = __ldg(csr + e2); ulonglong2 v = __ldg(Tp + s * 16u + l16); add2(a0, v.x); add2(a1, v.y); }
        if (e3 < end) { unsigned s = __ldg(csr + e3); ulonglong2 v = __ldg(Tp + s * 16u + l16); add2(b0, v.x); add2(b1, v.y); }
    }
    add2(a0, b0); add2(a1, b1);

    float f0, f1, f2, f3;
    unpack2(a0, f0, f1);
    unpack2(a1, f2, f3);
    f0 += __shfl_down_sync(0xffffffffu, f0, 16);
    f1 += __shfl_down_sync(0xffffffffu, f1, 16);
    f2 += __shfl_down_sync(0xffffffffu, f2, 16);
    f3 += __shfl_down_sync(0xffffffffu, f3, 16);

    if (half == 0) {
        float4 u = __ldg(reinterpret_cast<const float4*>(U) + (size_t)node * 16 + l16);
        float4 h;
        h.x = fmaxf(fmaf(f0, iv, u.x), 0.0f);
        h.y = fmaxf(fmaf(f1, iv, u.y), 0.0f);
        h.z = fmaxf(fmaf(f2, iv, u.z), 0.0f);
        h.w = fmaxf(fmaf(f3, iv, u.w), 0.0f);
        reinterpret_cast<float4*>(H)[(size_t)node * 16 + l16] = h;
    }
}

// DOUT=32: row = 128B = 8 lanes x float4; 4 edges/LDG; 2 chains = 8 edges/iter.
__global__ void __launch_bounds__(256)
gather32_kernel(const int* __restrict__ rs, const int* __restrict__ csr,
                const float* __restrict__ T, const float* __restrict__ U,
                const float* __restrict__ inv, float* __restrict__ H, int n) {
    int node = (blockIdx.x * blockDim.x + threadIdx.x) >> 5;
    if (node >= n) return;
    int lane = threadIdx.x & 31;
    unsigned q = lane >> 3, l8 = lane & 7;

    int beg = rs[node], end = rs[node + 1];
    float iv = inv[node];
    const ulonglong2* Tp = reinterpret_cast<const ulonglong2*>(T);  // 8 per row

    unsigned long long a0 = 0, a1 = 0, b0 = 0, b1 = 0;

    int i = beg;
    int s0, s1;
    bool have = (i + 8 <= end);
    if (have) {
        s0 = __ldg(csr + i + q);
        s1 = __ldg(csr + i + 4 + q);
    }
    while (have) {
        ulonglong2 v0 = __ldg(Tp + (unsigned)s0 * 8u + l8);
        ulonglong2 v1 = __ldg(Tp + (unsigned)s1 * 8u + l8);
        i += 8;
        have = (i + 8 <= end);
        if (have) {
            s0 = __ldg(csr + i + q);
            s1 = __ldg(csr + i + 4 + q);
        }
        add2(a0, v0.x); add2(a1, v0.y);
        add2(b0, v1.x); add2(b1, v1.y);
    }
    {
        int e0 = i + q, e1 = i + 4 + q;
        if (e0 < end) { unsigned s = __ldg(csr + e0); ulonglong2 v = __ldg(Tp + s * 8u + l8); add2(a0, v.x); add2(a1, v.y); }
        if (e1 < end) { unsigned s = __ldg(csr + e1); ulonglong2 v = __ldg(Tp + s * 8u + l8); add2(b0, v.x); add2(b1, v.y); }
    }
    add2(a0, b0); add2(a1, b1);

    float f0, f1, f2, f3;
    unpack2(a0, f0, f1);
    unpack2(a1, f2, f3);
#pragma unroll
    for (int off = 8; off <= 16; off <<= 1) {
        f0 += __shfl_down_sync(0xffffffffu, f0, off);
        f1 += __shfl_down_sync(0xffffffffu, f1, off);
        f2 += __shfl_down_sync(0xffffffffu, f2, off);
        f3 += __shfl_down_sync(0xffffffffu, f3, off);
    }

    if (q == 0) {
        float4 u = __ldg(reinterpret_cast<const float4*>(U) + (size_t)node * 8 + l8);
        float4 h;
        h.x = fmaxf(fmaf(f0, iv, u.x), 0.0f);
        h.y = fmaxf(fmaf(f1, iv, u.y), 0.0f);
        h.z = fmaxf(fmaf(f2, iv, u.z), 0.0f);
        h.w = fmaxf(fmaf(f3, iv, u.w), 0.0f);
        reinterpret_cast<float4*>(H)[(size_t)node * 8 + l8] = h;
    }
}

// DOUT=16 + fused head: row = 64B = 4 lanes x float4; 8 edges/LDG;
// 2 chains = 16 edges/iter.
__global__ void __launch_bounds__(256)
gather16_head_kernel(const int* __restrict__ rs, const int* __restrict__ csr,
                     const float* __restrict__ T, const float* __restrict__ U,
                     const float* __restrict__ inv,
                     const float* __restrict__ Wc, const float* __restrict__ bc,
                     float* __restrict__ out, int n) {
    int node = (blockIdx.x * blockDim.x + threadIdx.x) >> 5;
    if (node >= n) return;
    int lane = threadIdx.x & 31;
    unsigned g = lane >> 2, l4 = lane & 3;

    int beg = rs[node], end = rs[node + 1];
    float iv = inv[node];
    const ulonglong2* Tp = reinterpret_cast<const ulonglong2*>(T);  // 4 per row

    unsigned long long a0 = 0, a1 = 0, b0 = 0, b1 = 0;

    int i = beg;
    int s0, s1;
    bool have = (i + 16 <= end);
    if (have) {
        s0 = __ldg(csr + i + g);
        s1 = __ldg(csr + i + 8 + g);
    }
    while (have) {
        ulonglong2 v0 = __ldg(Tp + (unsigned)s0 * 4u + l4);
        ulonglong2 v1 = __ldg(Tp + (unsigned)s1 * 4u + l4);
        i += 16;
        have = (i + 16 <= end);
        if (have) {
            s0 = __ldg(csr + i + g);
            s1 = __ldg(csr + i + 8 + g);
        }
        add2(a0, v0.x); add2(a1, v0.y);
        add2(b0, v1.x); add2(b1, v1.y);
    }
    {
        int e0 = i + g, e1 = i + 8 + g;
        if (e0 < end) { unsigned s = __ldg(csr + e0); ulonglong2 v = __ldg(Tp + s * 4u + l4); add2(a0, v.x); add2(a1, v.y); }
        if (e1 < end) { unsigned s = __ldg(csr + e1); ulonglong2 v = __ldg(Tp + s * 4u + l4); add2(b0, v.x); add2(b1, v.y); }
    }
    add2(a0, b0); add2(a1, b1);

    float f0, f1, f2, f3;
    unpack2(a0, f0, f1);
    unpack2(a1, f2, f3);
#pragma unroll
    for (int off = 4; off <= 16; off <<= 1) {
        f0 += __shfl_down_sync(0xffffffffu, f0, off);
        f1 += __shfl_down_sync(0xffffffffu, f1, off);
        f2 += __shfl_down_sync(0xffffffffu, f2, off);
        f3 += __shfl_down_sync(0xffffffffu, f3, off);
    }

    // lanes 0-3 hold cols l4*4 .. l4*4+3; combine + fused 16->1 head
    float partial = 0.0f;
    if (lane < 4) {
        float4 u = __ldg(reinterpret_cast<const float4*>(U) + (size_t)node * 4 + l4);
        float4 w = __ldg(reinterpret_cast<const float4*>(Wc) + l4);
        float h0 = fmaxf(fmaf(f0, iv, u.x), 0.0f);
        float h1 = fmaxf(fmaf(f1, iv, u.y), 0.0f);
        float h2 = fmaxf(fmaf(f2, iv, u.z), 0.0f);
        float h3 = fmaxf(fmaf(f3, iv, u.w), 0.0f);
        partial = h0 * w.x + h1 * w.y + h2 * w.z + h3 * w.w;
    }
    partial += __shfl_down_sync(0xffffffffu, partial, 2);
    partial += __shfl_down_sync(0xffffffffu, partial, 1);
    if (lane == 0) out[node] = partial + __ldg(bc);
}

// ---------------------------------------------------------------------------

template <int DIN, int DOUT>
static void launch_gemm(const float* X, const float* Wl, const float* Wr,
                        const float* B, float* T, float* U, int n) {
    constexpr int BT = 8 * 8 * (32 / (DOUT / 2));
    constexpr int SMEM = (DIN * 2 * DOUT + BT * (DIN + 4)) * (int)sizeof(float);
    int ntiles = cdiv(n, BT);
    cudaFuncSetAttribute(gemm_kernel<DIN, DOUT>,
                         cudaFuncAttributeMaxDynamicSharedMemorySize, SMEM);
    int grid = ntiles < 592 ? ntiles : 592;
    gemm_kernel<DIN, DOUT><<<grid, 256, SMEM>>>(X, Wl, Wr, B, T, U, n, ntiles);
}

extern "C" void kernel_launch(void* const* d_in, const int* in_sizes, int n_in,
                              void* d_out, int out_size) {
    const float* x   = (const float*)d_in[0];
    const int* eidx  = (const int*)d_in[1];
    const float* Wl0 = (const float*)d_in[2];
    const float* Wr0 = (const float*)d_in[3];
    const float* b0  = (const float*)d_in[4];
    const float* Wl1 = (const float*)d_in[5];
    const float* Wr1 = (const float*)d_in[6];
    const float* b1  = (const float*)d_in[7];
    const float* Wl2 = (const float*)d_in[8];
    const float* Wr2 = (const float*)d_in[9];
    const float* b2  = (const float*)d_in[10];
    const float* Wc  = (const float*)d_in[11];
    const float* bc  = (const float*)d_in[12];
    float* out = (float*)d_out;

    const int n = in_sizes[0] / 64;        // 100000
    const int e = in_sizes[1] / 2;         // 3200000
    const int* src = eidx;
    const int* dst = eidx + e;

    float *t, *u, *h, *inv;
    int *cnt, *rs, *cur, *csr, *bsum;
    cudaGetSymbolAddress((void**)&t, g_t);
    cudaGetSymbolAddress((void**)&u, g_u);
    cudaGetSymbolAddress((void**)&h, g_h);
    cudaGetSymbolAddress((void**)&inv, g_inv);
    cudaGetSymbolAddress((void**)&cnt, g_cnt);
    cudaGetSymbolAddress((void**)&rs, g_rs);
    cudaGetSymbolAddress((void**)&cur, g_cur);
    cudaGetSymbolAddress((void**)&csr, g_csr);
    cudaGetSymbolAddress((void**)&bsum, g_bsum);

    const int nb = cdiv(n, 256);

    // --- CSR + inv_deg (built once, reused 3x) ---
    zero_cnt_kernel<<<cdiv(n, 256), 256>>>(cnt, n);
    hist_kernel<<<cdiv(e, 256), 256>>>(dst, cnt, e);
    scan1_kernel<<<nb, 256>>>(cnt, rs, bsum, n);
    scan2_kernel<<<1, 512>>>(bsum, nb);
    scan3_kernel<<<nb, 256>>>(cnt, rs, cur, inv, bsum, n);
    fill_kernel<<<cdiv(e, 256), 256>>>(src, dst, cur, csr, e);

    // --- layer 0: 64 -> 64 ---
    launch_gemm<64, 64>(x, Wl0, Wr0, b0, t, u, n);
    gather64_kernel<<<cdiv((long long)n * 32, 256), 256>>>(rs, csr, t, u, inv, h, n);

    // --- layer 1: 64 -> 32 ---
    launch_gemm<64, 32>(h, Wl1, Wr1, b1, t, u, n);
    gather32_kernel<<<cdiv((long long)n * 32, 256), 256>>>(rs, csr, t, u, inv, h, n);

    // --- layer 2: 32 -> 16, fused with 16 -> 1 head ---
    launch_gemm<32, 16>(h, Wl2, Wr2, b2, t, u, n);
    gather16_head_kernel<<<cdiv((long long)n * 32, 256), 256>>>(rs, csr, t, u, inv,
                                                                Wc, bc, out, n);
}

// round 11
// speedup vs baseline: 1.1708x; 1.0754x over previous
#include <cuda_runtime.h>
#include <cuda_fp16.h>
#include <cstdint>

// ---------------------------------------------------------------------------
// GraphSAGE: 3x SAGEConv(mean) + linear head.
// N=100000, E=3200000, dims 64 -> 64 -> 32 -> 16 -> 1
//
// v11: fp16 T + HADD2 packed accumulation (no per-edge convert stream),
//      single fp32 fold per node. Halves L1tex lines/edge AND keeps
//      instructions/edge minimal — addresses the measured wavefront floor.
//      v10 CSR chain + f32x2 GEMMs unchanged.
// ---------------------------------------------------------------------------

#define N_NODES 100000
#define MAX_E   3200000

__device__ __half g_t[(size_t)N_NODES * 64];
__device__ float  g_u[(size_t)N_NODES * 64];
__device__ float  g_h[(size_t)N_NODES * 64];
__device__ float  g_inv[N_NODES];
__device__ int    g_cnt[N_NODES];
__device__ int    g_rs[N_NODES + 1];
__device__ int    g_cur[N_NODES];
__device__ int    g_csr[MAX_E];
__device__ int    g_bsum[512];

static inline int cdiv(long long a, int b) { return (int)((a + b - 1) / b); }

// ---------------- helpers ----------------
__device__ __forceinline__ unsigned long long dup2(float a) {
    unsigned long long r;
    asm("mov.b64 %0, {%1, %1};" : "=l"(r) : "f"(a));
    return r;
}
__device__ __forceinline__ unsigned long long pack2(float a, float b) {
    unsigned long long r;
    asm("mov.b64 %0, {%1, %2};" : "=l"(r) : "f"(a), "f"(b));
    return r;
}
__device__ __forceinline__ void unpack2(unsigned long long v, float& a, float& b) {
    asm("mov.b64 {%0, %1}, %2;" : "=f"(a), "=f"(b) : "l"(v));
}
__device__ __forceinline__ void fma2(unsigned long long& acc,
                                     unsigned long long x, unsigned long long w) {
    asm("fma.rn.f32x2 %0, %1, %2, %0;" : "+l"(acc) : "l"(x), "l"(w));
}
__device__ __forceinline__ __half2 as_h2(unsigned int u) {
    return *reinterpret_cast<__half2*>(&u);
}
// accumulate a uint4 (8 halves) into 4 half2 accumulators — 4 HADD2
__device__ __forceinline__ void hacc4(__half2* a, const uint4& v) {
    a[0] = __hadd2(a[0], as_h2(v.x));
    a[1] = __hadd2(a[1], as_h2(v.y));
    a[2] = __hadd2(a[2], as_h2(v.z));
    a[3] = __hadd2(a[3], as_h2(v.w));
}

// ---------------- CSR build (v10 structure, measured) ----------------
__global__ void zero_cnt_kernel(int* __restrict__ cnt, int n) {
    int i = blockIdx.x * blockDim.x + threadIdx.x;
    if (i < n) cnt[i] = 0;
}

__global__ void hist_kernel(const int* __restrict__ dst, int* __restrict__ cnt, int e) {
    int i = blockIdx.x * blockDim.x + threadIdx.x;
    if (i < e) atomicAdd(&cnt[dst[i]], 1);
}

__global__ void __launch_bounds__(256)
scan1_kernel(const int* __restrict__ cnt, int* __restrict__ rs,
             int* __restrict__ bsum, int n) {
    __shared__ int sm[256];
    int tid = threadIdx.x;
    int gi = blockIdx.x * 256 + tid;
    int v = (gi < n) ? cnt[gi] : 0;
    sm[tid] = v;
    __syncthreads();
#pragma unroll
    for (int off = 1; off < 256; off <<= 1) {
        int t = (tid >= off) ? sm[tid - off] : 0;
        __syncthreads();
        sm[tid] += t;
        __syncthreads();
    }
    if (gi < n) rs[gi] = sm[tid] - v;
    if (tid == 255) bsum[blockIdx.x] = sm[255];
}

__global__ void __launch_bounds__(512)
scan2_kernel(int* __restrict__ bsum, int nb) {
    __shared__ int sm[512];
    int tid = threadIdx.x;
    int v = (tid < nb) ? bsum[tid] : 0;
    sm[tid] = v;
    __syncthreads();
#pragma unroll
    for (int off = 1; off < 512; off <<= 1) {
        int t = (tid >= off) ? sm[tid - off] : 0;
        __syncthreads();
        sm[tid] += t;
        __syncthreads();
    }
    if (tid < nb) bsum[tid] = sm[tid] - v;
}

__global__ void scan3_kernel(const int* __restrict__ cnt, int* __restrict__ rs,
                             int* __restrict__ cur, float* __restrict__ inv,
                             const int* __restrict__ bsum, int n) {
    int gi = blockIdx.x * blockDim.x + threadIdx.x;
    if (gi >= n) return;
    int rsv = rs[gi] + bsum[blockIdx.x];
    rs[gi] = rsv;
    cur[gi] = rsv;
    int c = cnt[gi];
    inv[gi] = 1.0f / fmaxf((float)c, 1.0f);
    if (gi == n - 1) rs[n] = rsv + c;
}

__global__ void fill_kernel(const int* __restrict__ src, const int* __restrict__ dst,
                            int* __restrict__ cur, int* __restrict__ csr, int e) {
    int i = blockIdx.x * blockDim.x + threadIdx.x;
    if (i < e) {
        int p = atomicAdd(&cur[dst[i]], 1);
        csr[p] = src[i];
    }
}

// ---------------- tiled dual GEMM: t(h16) = X@Wl, u(f32) = X@Wr + b --------
template <int DIN, int DOUT>
__global__ void __launch_bounds__(256)
gemm_kernel(const float* __restrict__ X,
            const float* __restrict__ Wl, const float* __restrict__ Wr,
            const float* __restrict__ B,
            __half* __restrict__ T, float* __restrict__ U,
            int n, int ntiles) {
    constexpr int P  = DOUT / 2;
    constexpr int G  = 32 / P;
    constexpr int WT = 8 * G;
    constexpr int BT = 8 * WT;
    constexpr int XP = DIN + 4;

    extern __shared__ float sm[];
    float* sW = sm;
    float* sX = sm + DIN * 2 * DOUT;

    for (int i = threadIdx.x; i < DIN * DOUT; i += 256) {
        int k = i / DOUT, j = i % DOUT;
        sW[k * 2 * DOUT + 4 * (j >> 1) + (j & 1)]     = Wl[i];
        sW[k * 2 * DOUT + 4 * (j >> 1) + 2 + (j & 1)] = Wr[i];
    }

    int lane = threadIdx.x & 31;
    int warp = threadIdx.x >> 5;
    int g = lane / P;
    int p = lane % P;

    float2 bb = *reinterpret_cast<const float2*>(B + 2 * p);

    for (int tile = blockIdx.x; tile < ntiles; tile += gridDim.x) {
        int nbase = tile * BT;
        __syncthreads();
        for (int i = threadIdx.x; i < BT * (DIN / 4); i += 256) {
            int node = i / (DIN / 4), kq = i % (DIN / 4);
            int gn = nbase + node;
            float4 v = make_float4(0.f, 0.f, 0.f, 0.f);
            if (gn < n) v = *reinterpret_cast<const float4*>(X + (size_t)gn * DIN + 4 * kq);
            *reinterpret_cast<float4*>(&sX[node * XP + 4 * kq]) = v;
        }
        __syncthreads();

        int ln = warp * WT + g * 8;

        unsigned long long aL0[4], aL1[4], aR0[4], aR1[4];
#pragma unroll
        for (int m = 0; m < 4; m++) {
            aL0[m] = 0ull; aL1[m] = 0ull;
            aR0[m] = dup2(bb.x); aR1[m] = dup2(bb.y);
        }

#pragma unroll 8
        for (int k = 0; k < DIN; k++) {
            float4 w = *reinterpret_cast<const float4*>(&sW[k * 2 * DOUT + 4 * p]);
            unsigned long long wl0 = dup2(w.x), wl1 = dup2(w.y);
            unsigned long long wr0 = dup2(w.z), wr1 = dup2(w.w);
            float xs[8];
#pragma unroll
            for (int m = 0; m < 8; m++) xs[m] = sX[(ln + m) * XP + k];
#pragma unroll
            for (int m = 0; m < 4; m++) {
                unsigned long long xp2 = pack2(xs[2 * m], xs[2 * m + 1]);
                fma2(aL0[m], xp2, wl0);
                fma2(aL1[m], xp2, wl1);
                fma2(aR0[m], xp2, wr0);
                fma2(aR1[m], xp2, wr1);
            }
        }

#pragma unroll
        for (int m = 0; m < 4; m++) {
            float l0a, l0b, l1a, l1b, r0a, r0b, r1a, r1b;
            unpack2(aL0[m], l0a, l0b);
            unpack2(aL1[m], l1a, l1b);
            unpack2(aR0[m], r0a, r0b);
            unpack2(aR1[m], r1a, r1b);
            int gn0 = nbase + ln + 2 * m;
            if (gn0 < n) {
                reinterpret_cast<__half2*>(T)[(size_t)gn0 * P + p] =
                    __floats2half2_rn(l0a, l1a);
                *reinterpret_cast<float2*>(&U[(size_t)gn0 * DOUT + 2 * p]) =
                    make_float2(r0a, r1a);
            }
            if (gn0 + 1 < n) {
                reinterpret_cast<__half2*>(T)[(size_t)(gn0 + 1) * P + p] =
                    __floats2half2_rn(l0b, l1b);
                *reinterpret_cast<float2*>(&U[(size_t)(gn0 + 1) * DOUT + 2 * p]) =
                    make_float2(r0b, r1b);
            }
        }
    }
}

// ---------------- gathers: fp16 rows, HADD2 accumulation, one fp32 fold ----

// DOUT=64: row = 128B = 8 lanes x uint4; 4 edges/LDG; 8 edges/iter.
__global__ void __launch_bounds__(256)
gather64_kernel(const int* __restrict__ rs, const int* __restrict__ csr,
                const __half* __restrict__ T, const float* __restrict__ U,
                const float* __restrict__ inv, float* __restrict__ H, int n) {
    int node = (blockIdx.x * blockDim.x + threadIdx.x) >> 5;
    if (node >= n) return;
    int lane = threadIdx.x & 31;
    unsigned q = lane >> 3, l8 = lane & 7;

    int beg = rs[node], end = rs[node + 1];
    float iv = inv[node];
    const uint4* Tp = reinterpret_cast<const uint4*>(T);   // 8 uint4 per row

    __half2 hA[4], hB[4];
#pragma unroll
    for (int j = 0; j < 4; j++) { hA[j] = __half2(); hB[j] = __half2(); }

    int i = beg;
    int s0, s1;
    bool have = (i + 8 <= end);
    if (have) {
        s0 = __ldg(csr + i + q);
        s1 = __ldg(csr + i + 4 + q);
    }
    while (have) {
        uint4 v0 = __ldg(Tp + (unsigned)s0 * 8u + l8);
        uint4 v1 = __ldg(Tp + (unsigned)s1 * 8u + l8);
        i += 8;
        have = (i + 8 <= end);
        if (have) {
            s0 = __ldg(csr + i + q);
            s1 = __ldg(csr + i + 4 + q);
        }
        hacc4(hA, v0);
        hacc4(hB, v1);
    }
    {   // tail < 8 edges: predicated dual chains
        int e0 = i + q, e1 = i + 4 + q;
        if (e0 < end) { unsigned s = __ldg(csr + e0); hacc4(hA, __ldg(Tp + s * 8u + l8)); }
        if (e1 < end) { unsigned s = __ldg(csr + e1); hacc4(hB, __ldg(Tp + s * 8u + l8)); }
    }

    // single fp32 fold per node
    float2 f[4];
#pragma unroll
    for (int j = 0; j < 4; j++) {
        float2 a = __half22float2(hA[j]);
        float2 b = __half22float2(hB[j]);
        f[j].x = a.x + b.x;
        f[j].y = a.y + b.y;
    }
#pragma unroll
    for (int off = 8; off <= 16; off <<= 1) {
#pragma unroll
        for (int j = 0; j < 4; j++) {
            f[j].x += __shfl_down_sync(0xffffffffu, f[j].x, off);
            f[j].y += __shfl_down_sync(0xffffffffu, f[j].y, off);
        }
    }

    if (q == 0) {   // lanes 0-7 hold cols l8*8 .. l8*8+7
        const float4* U4 = reinterpret_cast<const float4*>(U) + (size_t)node * 16 + l8 * 2;
        float4* H4 = reinterpret_cast<float4*>(H) + (size_t)node * 16 + l8 * 2;
        float4 u0 = __ldg(U4), u1 = __ldg(U4 + 1);
        float4 h0, h1;
        h0.x = fmaxf(fmaf(f[0].x, iv, u0.x), 0.0f);
        h0.y = fmaxf(fmaf(f[0].y, iv, u0.y), 0.0f);
        h0.z = fmaxf(fmaf(f[1].x, iv, u0.z), 0.0f);
        h0.w = fmaxf(fmaf(f[1].y, iv, u0.w), 0.0f);
        h1.x = fmaxf(fmaf(f[2].x, iv, u1.x), 0.0f);
        h1.y = fmaxf(fmaf(f[2].y, iv, u1.y), 0.0f);
        h1.z = fmaxf(fmaf(f[3].x, iv, u1.z), 0.0f);
        h1.w = fmaxf(fmaf(f[3].y, iv, u1.w), 0.0f);
        H4[0] = h0; H4[1] = h1;
    }
}

// DOUT=32: row = 64B = 4 lanes x uint4; 8 edges/LDG; 16 edges/iter.
__global__ void __launch_bounds__(256)
gather32_kernel(const int* __restrict__ rs, const int* __restrict__ csr,
                const __half* __restrict__ T, const float* __restrict__ U,
                const float* __restrict__ inv, float* __restrict__ H, int n) {
    int node = (blockIdx.x * blockDim.x + threadIdx.x) >> 5;
    if (node >= n) return;
    int lane = threadIdx.x & 31;
    unsigned g = lane >> 2, l4 = lane & 3;

    int beg = rs[node], end = rs[node + 1];
    float iv = inv[node];
    const uint4* Tp = reinterpret_cast<const uint4*>(T);   // 4 uint4 per row

    __half2 hA[4], hB[4];
#pragma unroll
    for (int j = 0; j < 4; j++) { hA[j] = __half2(); hB[j] = __half2(); }

    int i = beg;
    int s0, s1;
    bool have = (i + 16 <= end);
    if (have) {
        s0 = __ldg(csr + i + g);
        s1 = __ldg(csr + i + 8 + g);
    }
    while (have) {
        uint4 v0 = __ldg(Tp + (unsigned)s0 * 4u + l4);
        uint4 v1 = __ldg(Tp + (unsigned)s1 * 4u + l4);
        i += 16;
        have = (i + 16 <= end);
        if (have) {
            s0 = __ldg(csr + i + g);
            s1 = __ldg(csr + i + 8 + g);
        }
        hacc4(hA, v0);
        hacc4(hB, v1);
    }
    {
        int e0 = i + g, e1 = i + 8 + g;
        if (e0 < end) { unsigned s = __ldg(csr + e0); hacc4(hA, __ldg(Tp + s * 4u + l4)); }
        if (e1 < end) { unsigned s = __ldg(csr + e1); hacc4(hB, __ldg(Tp + s * 4u + l4)); }
    }

    float2 f[4];
#pragma unroll
    for (int j = 0; j < 4; j++) {
        float2 a = __half22float2(hA[j]);
        float2 b = __half22float2(hB[j]);
        f[j].x = a.x + b.x;
        f[j].y = a.y + b.y;
    }
#pragma unroll
    for (int off = 4; off <= 16; off <<= 1) {
#pragma unroll
        for (int j = 0; j < 4; j++) {
            f[j].x += __shfl_down_sync(0xffffffffu, f[j].x, off);
            f[j].y += __shfl_down_sync(0xffffffffu, f[j].y, off);
        }
    }

    if (g == 0) {   // lanes 0-3 hold cols l4*8 .. l4*8+7
        const float4* U4 = reinterpret_cast<const float4*>(U) + (size_t)node * 8 + l4 * 2;
        float4* H4 = reinterpret_cast<float4*>(H) + (size_t)node * 8 + l4 * 2;
        float4 u0 = __ldg(U4), u1 = __ldg(U4 + 1);
        float4 h0, h1;
        h0.x = fmaxf(fmaf(f[0].x, iv, u0.x), 0.0f);
        h0.y = fmaxf(fmaf(f[0].y, iv, u0.y), 0.0f);
        h0.z = fmaxf(fmaf(f[1].x, iv, u0.z), 0.0f);
        h0.w = fmaxf(fmaf(f[1].y, iv, u0.w), 0.0f);
        h1.x = fmaxf(fmaf(f[2].x, iv, u1.x), 0.0f);
        h1.y = fmaxf(fmaf(f[2].y, iv, u1.y), 0.0f);
        h1.z = fmaxf(fmaf(f[3].x, iv, u1.z), 0.0f);
        h1.w = fmaxf(fmaf(f[3].y, iv, u1.w), 0.0f);
        H4[0] = h0; H4[1] = h1;
    }
}

// DOUT=16 + fused head: row = 32B = 2 lanes x uint4; 16 edges/LDG; 32/iter.
__global__ void __launch_bounds__(256)
gather16_head_kernel(const int* __restrict__ rs, const int* __restrict__ csr,
                     const __half* __restrict__ T, const float* __restrict__ U,
                     const float* __restrict__ inv,
                     const float* __restrict__ Wc, const float* __restrict__ bc,
                     float* __restrict__ out, int n) {
    int node = (blockIdx.x * blockDim.x + threadIdx.x) >> 5;
    if (node >= n) return;
    int lane = threadIdx.x & 31;
    unsigned g = lane >> 1, l2 = lane & 1;

    int beg = rs[node], end = rs[node + 1];
    float iv = inv[node];
    const uint4* Tp = reinterpret_cast<const uint4*>(T);   // 2 uint4 per row

    __half2 hA[4], hB[4];
#pragma unroll
    for (int j = 0; j < 4; j++) { hA[j] = __half2(); hB[j] = __half2(); }

    int i = beg;
    int s0, s1;
    bool have = (i + 32 <= end);
    if (have) {
        s0 = __ldg(csr + i + g);
        s1 = __ldg(csr + i + 16 + g);
    }
    while (have) {
        uint4 v0 = __ldg(Tp + (unsigned)s0 * 2u + l2);
        uint4 v1 = __ldg(Tp + (unsigned)s1 * 2u + l2);
        i += 32;
        have = (i + 32 <= end);
        if (have) {
            s0 = __ldg(csr + i + g);
            s1 = __ldg(csr + i + 16 + g);
        }
        hacc4(hA, v0);
        hacc4(hB, v1);
    }
    {
        int e0 = i + g, e1 = i + 16 + g;
        if (e0 < end) { unsigned s = __ldg(csr + e0); hacc4(hA, __ldg(Tp + s * 2u + l2)); }
        if (e1 < end) { unsigned s = __ldg(csr + e1); hacc4(hB, __ldg(Tp + s * 2u + l2)); }
    }

    float2 f[4];
#pragma unroll
    for (int j = 0; j < 4; j++) {
        float2 a = __half22float2(hA[j]);
        float2 b = __half22float2(hB[j]);
        f[j].x = a.x + b.x;
        f[j].y = a.y + b.y;
    }
#pragma unroll
    for (int off = 2; off <= 16; off <<= 1) {
#pragma unroll
        for (int j = 0; j < 4; j++) {
            f[j].x += __shfl_down_sync(0xffffffffu, f[j].x, off);
            f[j].y += __shfl_down_sync(0xffffffffu, f[j].y, off);
        }
    }

    // lanes 0-1 hold cols l2*8 .. l2*8+7; combine + fused 16->1 head
    float partial = 0.0f;
    if (lane < 2) {
        const float4* U4 = reinterpret_cast<const float4*>(U) + (size_t)node * 4 + l2 * 2;
        float4 u0 = __ldg(U4), u1 = __ldg(U4 + 1);
        const float4* W4 = reinterpret_cast<const float4*>(Wc) + l2 * 2;
        float4 w0 = __ldg(W4), w1 = __ldg(W4 + 1);
        float h0 = fmaxf(fmaf(f[0].x, iv, u0.x), 0.0f);
        float h1 = fmaxf(fmaf(f[0].y, iv, u0.y), 0.0f);
        float h2 = fmaxf(fmaf(f[1].x, iv, u0.z), 0.0f);
        float h3 = fmaxf(fmaf(f[1].y, iv, u0.w), 0.0f);
        float h4 = fmaxf(fmaf(f[2].x, iv, u1.x), 0.0f);
        float h5 = fmaxf(fmaf(f[2].y, iv, u1.y), 0.0f);
        float h6 = fmaxf(fmaf(f[3].x, iv, u1.z), 0.0f);
        float h7 = fmaxf(fmaf(f[3].y, iv, u1.w), 0.0f);
        partial = h0 * w0.x + h1 * w0.y + h2 * w0.z + h3 * w0.w
                + h4 * w1.x + h5 * w1.y + h6 * w1.z + h7 * w1.w;
    }
    partial += __shfl_down_sync(0xffffffffu, partial, 1);
    if (lane == 0) out[node] = partial + __ldg(bc);
}

// ---------------------------------------------------------------------------

template <int DIN, int DOUT>
static void launch_gemm(const float* X, const float* Wl, const float* Wr,
                        const float* B, __half* T, float* U, int n) {
    constexpr int BT = 8 * 8 * (32 / (DOUT / 2));
    constexpr int SMEM = (DIN * 2 * DOUT + BT * (DIN + 4)) * (int)sizeof(float);
    int ntiles = cdiv(n, BT);
    cudaFuncSetAttribute(gemm_kernel<DIN, DOUT>,
                         cudaFuncAttributeMaxDynamicSharedMemorySize, SMEM);
    int grid = ntiles < 592 ? ntiles : 592;
    gemm_kernel<DIN, DOUT><<<grid, 256, SMEM>>>(X, Wl, Wr, B, T, U, n, ntiles);
}

extern "C" void kernel_launch(void* const* d_in, const int* in_sizes, int n_in,
                              void* d_out, int out_size) {
    const float* x   = (const float*)d_in[0];
    const int* eidx  = (const int*)d_in[1];
    const float* Wl0 = (const float*)d_in[2];
    const float* Wr0 = (const float*)d_in[3];
    const float* b0  = (const float*)d_in[4];
    const float* Wl1 = (const float*)d_in[5];
    const float* Wr1 = (const float*)d_in[6];
    const float* b1  = (const float*)d_in[7];
    const float* Wl2 = (const float*)d_in[8];
    const float* Wr2 = (const float*)d_in[9];
    const float* b2  = (const float*)d_in[10];
    const float* Wc  = (const float*)d_in[11];
    const float* bc  = (const float*)d_in[12];
    float* out = (float*)d_out;

    const int n = in_sizes[0] / 64;        // 100000
    const int e = in_sizes[1] / 2;         // 3200000
    const int* src = eidx;
    const int* dst = eidx + e;

    __half* t;
    float *u, *h, *inv;
    int *cnt, *rs, *cur, *csr, *bsum;
    cudaGetSymbolAddress((void**)&t, g_t);
    cudaGetSymbolAddress((void**)&u, g_u);
    cudaGetSymbolAddress((void**)&h, g_h);
    cudaGetSymbolAddress((void**)&inv, g_inv);
    cudaGetSymbolAddress((void**)&cnt, g_cnt);
    cudaGetSymbolAddress((void**)&rs, g_rs);
    cudaGetSymbolAddress((void**)&cur, g_cur);
    cudaGetSymbolAddress((void**)&csr, g_csr);
    cudaGetSymbolAddress((void**)&bsum, g_bsum);

    const int nb = cdiv(n, 256);

    // --- CSR + inv_deg (built once, reused 3x) ---
    zero_cnt_kernel<<<cdiv(n, 256), 256>>>(cnt, n);
    hist_kernel<<<cdiv(e, 256), 256>>>(dst, cnt, e);
    scan1_kernel<<<nb, 256>>>(cnt, rs, bsum, n);
    scan2_kernel<<<1, 512>>>(bsum, nb);
    scan3_kernel<<<nb, 256>>>(cnt, rs, cur, inv, bsum, n);
    fill_kernel<<<cdiv(e, 256), 256>>>(src, dst, cur, csr, e);

    // --- layer 0: 64 -> 64 ---
    launch_gemm<64, 64>(x, Wl0, Wr0, b0, t, u, n);
    gather64_kernel<<<cdiv((long long)n * 32, 256), 256>>>(rs, csr, t, u, inv, h, n);

    // --- layer 1: 64 -> 32 ---
    launch_gemm<64, 32>(h, Wl1, Wr1, b1, t, u, n);
    gather32_kernel<<<cdiv((long long)n * 32, 256), 256>>>(rs, csr, t, u, inv, h, n);

    // --- layer 2: 32 -> 16, fused with 16 -> 1 head ---
    launch_gemm<32, 16>(h, Wl2, Wr2, b2, t, u, n);
    gather16_head_kernel<<<cdiv((long long)n * 32, 256), 256>>>(rs, csr, t, u, inv,
                                                                Wc, bc, out, n);
}